// round 13
// baseline (speedup 1.0000x reference)
#include <cuda_runtime.h>
#include <cuda_fp16.h>

// ---------------- problem constants ----------------
#define NNODES 100000
#define NEDGES 1600000
#define IN_DIM 8
#define HID    32
#define HEADS  4
#define F1     (HEADS * HID)       // 128
#define OUT_DIM 16
#define STRIDE 128                 // fixed adjacency bucket per node
#define FULLMASK 0xffffffffu

// ---------------- scratch (device globals; no allocation allowed) ----------------
__device__ __align__(16) float g_as1[NNODES * HEADS];
__device__ __align__(16) float g_ad1[NNODES * HEADS];
__device__ __align__(16) float g_xagg[NNODES * 32];        // 12.8 MB x-space aggregates
__device__ __align__(16) __half g_h2h[NNODES * OUT_DIM];   // 3.2 MB fp16 layer-2 features
__device__ __align__(16) float g_as2[NNODES];
__device__ __align__(16) float g_ad2[NNODES];
__device__ __align__(16) int g_srcs[NNODES * STRIDE];      // stores src*4 (pre-scaled)
__device__ int g_cnt[NNODES];
__device__ int g_is64;

// ---------------- helpers ----------------
__device__ __forceinline__ float elu_fast(float v) {
    return v > 0.f ? v : (__expf(v) - 1.f);
}
__device__ __forceinline__ float lrelu_exp(float e) {
    e = fmaxf(e, 0.2f * e);
    return __expf(e);
}
__device__ __forceinline__ unsigned pack2(float a, float b) {
    __half2 h = __floats2half2_rn(a, b);
    return *(unsigned*)&h;
}

// ---------------- K init: bucket init + self loop + probe + layer-1 logits (fused node1) ----------------
__global__ void __launch_bounds__(256) k_init(
        const void* __restrict__ ei,
        const float* __restrict__ x, const float* __restrict__ W1,
        const float* __restrict__ as1v, const float* __restrict__ ad1v) {
    __shared__ float sVa[IN_DIM][HEADS], sVd[IN_DIM][HEADS];
    int t = threadIdx.x;
    if (t < IN_DIM * HEADS) {
        int d = t >> 2, h = t & 3;
        float sa = 0.f, sd = 0.f;
        #pragma unroll
        for (int k = 0; k < HID; k++) {
            float w = W1[d * F1 + h * HID + k];
            sa = fmaf(w, as1v[h * HID + k], sa);
            sd = fmaf(w, ad1v[h * HID + k], sd);
        }
        sVa[d][h] = sa;
        sVd[d][h] = sd;
    }
    if (blockIdx.x == 0 && t == 0) {
        const unsigned* wrd = (const unsigned*)ei;
        int is64 = 1;
        #pragma unroll
        for (int i = 0; i < 32; i++)
            if (wrd[2 * i + 1] != 0u) { is64 = 0; break; }
        g_is64 = is64;
    }
    __syncthreads();

    int n = blockIdx.x * blockDim.x + t;
    if (n >= NNODES) return;

    g_cnt[n] = 1;
    g_srcs[n * STRIDE] = n * 4;            // self loop in slot 0 (pre-scaled)

    float4 x0 = *(const float4*)(x + n * IN_DIM);
    float4 x1 = *(const float4*)(x + n * IN_DIM + 4);
    float xv[IN_DIM] = {x0.x, x0.y, x0.z, x0.w, x1.x, x1.y, x1.z, x1.w};
    float oa[HEADS] = {0.f, 0.f, 0.f, 0.f};
    float od[HEADS] = {0.f, 0.f, 0.f, 0.f};
    #pragma unroll
    for (int d = 0; d < IN_DIM; d++) {
        #pragma unroll
        for (int h = 0; h < HEADS; h++) {
            oa[h] = fmaf(xv[d], sVa[d][h], oa[h]);
            od[h] = fmaf(xv[d], sVd[d][h], od[h]);
        }
    }
    *(float4*)&g_as1[n * HEADS] = make_float4(oa[0], oa[1], oa[2], oa[3]);
    *(float4*)&g_ad1[n * HEADS] = make_float4(od[0], od[1], od[2], od[3]);
}

// ---------------- K scatter: real edges into fixed-stride buckets (2 per thread) ----------------
__global__ void k_scatter(const void* __restrict__ ei) {
    int base = (blockIdx.x * blockDim.x + threadIdx.x) * 2;
    if (base >= NEDGES) return;
    int s0, s1 = -1, d0, d1 = 0;
    if (g_is64) {
        const long long* ps = (const long long*)ei;
        const long long* pd = ps + NEDGES;
        longlong2 sv = *(const longlong2*)(ps + base);
        longlong2 dv = *(const longlong2*)(pd + base);
        s0 = (int)sv.x; d0 = (int)dv.x;
        if (base + 1 < NEDGES) { s1 = (int)sv.y; d1 = (int)dv.y; }
    } else {
        const int* ps = (const int*)ei;
        const int* pd = ps + NEDGES;
        int2 sv = *(const int2*)(ps + base);
        int2 dv = *(const int2*)(pd + base);
        s0 = sv.x; d0 = dv.x;
        if (base + 1 < NEDGES) { s1 = sv.y; d1 = dv.y; }
    }
    int k0 = atomicAdd(&g_cnt[d0], 1);
    if (k0 < STRIDE) g_srcs[d0 * STRIDE + k0] = s0 * 4;
    if (s1 >= 0) {
        int k1 = atomicAdd(&g_cnt[d1], 1);
        if (k1 < STRIDE) g_srcs[d1 * STRIDE + k1] = s1 * 4;
    }
}

// ---------------- K agg1: edge loop ONLY -> normalized x-space aggregates ----------------
// warp per node; slot g = lane>>3 (4 edges/iter), hd = lane&7: head = hd&3, dq = hd>>2
__global__ void __launch_bounds__(256) k_agg1(const float* __restrict__ x) {
    int w = threadIdx.x >> 5, lane = threadIdx.x & 31;
    int n = blockIdx.x * 8 + w;              // 12500*8 == 100000
    int g = lane >> 3;
    int hd = lane & 7;
    int head = hd & 3;
    int dqc = (hd >> 2) * 4;                 // 0 or 4

    float ad_h = g_ad1[n * HEADS + head];
    int cnt = min(g_cnt[n], STRIDE);
    const int* my_srcs = &g_srcs[n * STRIDE];

    float4 acc = make_float4(0.f, 0.f, 0.f, 0.f);
    float den = 0.f;

    #pragma unroll 2
    for (int base = 0; base < cnt; base += 4) {
        int i = base + g;
        bool valid = i < cnt;
        int s4 = my_srcs[valid ? i : 0];     // slot 0 (self loop) always valid
        float e = g_as1[s4 + head];
        float4 xv = *(const float4*)(x + (s4 << 1) + dqc);
        float wgt = valid ? lrelu_exp(e + ad_h) : 0.f;
        acc.x = fmaf(xv.x, wgt, acc.x);
        acc.y = fmaf(xv.y, wgt, acc.y);
        acc.z = fmaf(xv.z, wgt, acc.z);
        acc.w = fmaf(xv.w, wgt, acc.w);
        den += wgt;
    }

    // combine the 4 edge slots (lane xor 8, 16)
    #pragma unroll
    for (int bit = 8; bit <= 16; bit <<= 1) {
        acc.x += __shfl_xor_sync(FULLMASK, acc.x, bit);
        acc.y += __shfl_xor_sync(FULLMASK, acc.y, bit);
        acc.z += __shfl_xor_sync(FULLMASK, acc.z, bit);
        acc.w += __shfl_xor_sync(FULLMASK, acc.w, bit);
        den   += __shfl_xor_sync(FULLMASK, den,   bit);
    }

    if (g == 0) {
        float inv = 1.f / (den + 1e-16f);
        float4 o = make_float4(acc.x * inv, acc.y * inv, acc.z * inv, acc.w * inv);
        *(float4*)&g_xagg[n * 32 + hd * 4] = o;   // 8 lanes x 16B = 128B coalesced
    }
}

// ---------------- K dense v3: 2 threads per node (parity owns 2 heads), high occupancy ----------------
// hc = elu(xagg@W1+b1) for this thread's 64 channels; partial p[16] = hc@W2;
// pair-combined via shfl_xor(.,1). All smem reads are warp-broadcast or pair-uniform.
__global__ void __launch_bounds__(256) k_dense(
        const float* __restrict__ W1, const float* __restrict__ b1,
        const float* __restrict__ W2,
        const float* __restrict__ as2v, const float* __restrict__ ad2v) {
    __shared__ __align__(16) float sW1[IN_DIM][F1];      // [d][c]
    __shared__ __align__(16) float sW2[F1][OUT_DIM];     // [c][o]
    __shared__ __align__(16) float sB1[F1];
    __shared__ float sAs[OUT_DIM], sAd[OUT_DIM];
    int t = threadIdx.x;
    for (int i = t; i < IN_DIM * F1; i += 256) ((float*)sW1)[i] = W1[i];
    for (int i = t; i < F1 * OUT_DIM; i += 256) ((float*)sW2)[i] = W2[i];
    if (t < F1) sB1[t] = b1[t];
    if (t < OUT_DIM) { sAs[t] = as2v[t]; sAd[t] = ad2v[t]; }
    __syncthreads();

    int tid = blockIdx.x * 256 + t;
    int n = tid >> 1;
    int ph = tid & 1;            // parity: heads {2ph, 2ph+1}
    if (n >= NNODES) return;

    float p[OUT_DIM];
    #pragma unroll
    for (int o = 0; o < OUT_DIM; o++) p[o] = 0.f;

    #pragma unroll
    for (int hh = 0; hh < 2; hh++) {
        int h = ph * 2 + hh;
        float x8[8];
        *(float4*)&x8[0] = *(const float4*)&g_xagg[n * 32 + h * 4];
        *(float4*)&x8[4] = *(const float4*)&g_xagg[n * 32 + 16 + h * 4];
        #pragma unroll 1
        for (int cq = 0; cq < 8; cq++) {
            int c = h * 32 + cq * 4;
            float4 hc = *(const float4*)&sB1[c];
            #pragma unroll
            for (int d = 0; d < IN_DIM; d++) {
                float4 wv = *(const float4*)&sW1[d][c];
                hc.x = fmaf(x8[d], wv.x, hc.x);
                hc.y = fmaf(x8[d], wv.y, hc.y);
                hc.z = fmaf(x8[d], wv.z, hc.z);
                hc.w = fmaf(x8[d], wv.w, hc.w);
            }
            hc.x = elu_fast(hc.x);
            hc.y = elu_fast(hc.y);
            hc.z = elu_fast(hc.z);
            hc.w = elu_fast(hc.w);
            float hcv[4] = {hc.x, hc.y, hc.z, hc.w};
            #pragma unroll
            for (int k = 0; k < 4; k++) {
                float4 w0 = *(const float4*)&sW2[c + k][0];
                float4 w1 = *(const float4*)&sW2[c + k][4];
                float4 w2v = *(const float4*)&sW2[c + k][8];
                float4 w3 = *(const float4*)&sW2[c + k][12];
                float hk = hcv[k];
                p[0]  = fmaf(hk, w0.x,  p[0]);
                p[1]  = fmaf(hk, w0.y,  p[1]);
                p[2]  = fmaf(hk, w0.z,  p[2]);
                p[3]  = fmaf(hk, w0.w,  p[3]);
                p[4]  = fmaf(hk, w1.x,  p[4]);
                p[5]  = fmaf(hk, w1.y,  p[5]);
                p[6]  = fmaf(hk, w1.z,  p[6]);
                p[7]  = fmaf(hk, w1.w,  p[7]);
                p[8]  = fmaf(hk, w2v.x, p[8]);
                p[9]  = fmaf(hk, w2v.y, p[9]);
                p[10] = fmaf(hk, w2v.z, p[10]);
                p[11] = fmaf(hk, w2v.w, p[11]);
                p[12] = fmaf(hk, w3.x,  p[12]);
                p[13] = fmaf(hk, w3.y,  p[13]);
                p[14] = fmaf(hk, w3.z,  p[14]);
                p[15] = fmaf(hk, w3.w,  p[15]);
            }
        }
    }

    // combine the two parity threads (adjacent lanes)
    #pragma unroll
    for (int o = 0; o < OUT_DIM; o++)
        p[o] += __shfl_xor_sync(FULLMASK, p[o], 1);

    if (ph == 0) {
        uint4 u0, u1;
        u0.x = pack2(p[0],  p[1]);  u0.y = pack2(p[2],  p[3]);
        u0.z = pack2(p[4],  p[5]);  u0.w = pack2(p[6],  p[7]);
        u1.x = pack2(p[8],  p[9]);  u1.y = pack2(p[10], p[11]);
        u1.z = pack2(p[12], p[13]); u1.w = pack2(p[14], p[15]);
        ((uint4*)g_h2h)[n * 2 + 0] = u0;
        ((uint4*)g_h2h)[n * 2 + 1] = u1;

        float ts = 0.f, td = 0.f;
        #pragma unroll
        for (int o = 0; o < OUT_DIM; o++) {
            ts = fmaf(p[o], sAs[o], ts);
            td = fmaf(p[o], sAd[o], td);
        }
        g_as2[n] = ts;
        g_ad2[n] = td;
    }
}

// ---------------- K agg2: layer-2 aggregate (8 edges/warp/iter, fp16 gather) + classifier ----------------
__global__ void __launch_bounds__(512) k_agg2(
        const float* __restrict__ b2, const float* __restrict__ Wc1,
        const float* __restrict__ bc1, const float* __restrict__ Wc2,
        const float* __restrict__ bc2, float* __restrict__ out,
        long long out_size) {
    __shared__ __align__(16) float sEmb[16][OUT_DIM + 4];  // 80B rows (16B multiple)
    __shared__ float sT[16][9];
    __shared__ float sWc1[OUT_DIM * 8];
    __shared__ float sWc2[8], sB2[OUT_DIM];
    __shared__ float sBc1[8], sBc2;
    int t = threadIdx.x;
    if (t < OUT_DIM * 8) sWc1[t] = Wc1[t];
    if (t >= 128 && t < 136) sWc2[t - 128] = Wc2[t - 128];
    if (t >= 136 && t < 144) sBc1[t - 136] = bc1[t - 136];
    if (t >= 144 && t < 160) sB2[t - 144] = b2[t - 144];
    if (t == 160) sBc2 = bc2[0];
    __syncthreads();

    int w = t >> 5, lane = t & 31;
    int n = blockIdx.x * 16 + w;
    int g2 = lane >> 2;        // edge slot 0..7
    int q4 = lane & 3;         // channel quad 4q4..4q4+3

    float ad_n = g_ad2[n];
    int cnt = min(g_cnt[n], STRIDE);
    const int* my_srcs = &g_srcs[n * STRIDE];

    float4 acc = make_float4(0.f, 0.f, 0.f, 0.f);
    float den = 0.f;

    for (int base = 0; base < cnt; base += 8) {
        int i = base + g2;
        bool valid = i < cnt;
        int s4 = my_srcs[valid ? i : 0];
        float e = g_as2[s4 >> 2];
        uint2 hv = ((const uint2*)g_h2h)[s4 + q4];        // 8B = 4 fp16 channels
        float wgt = valid ? lrelu_exp(e + ad_n) : 0.f;
        float2 f01 = __half22float2(*(const __half2*)&hv.x);
        float2 f23 = __half22float2(*(const __half2*)&hv.y);
        acc.x = fmaf(f01.x, wgt, acc.x);
        acc.y = fmaf(f01.y, wgt, acc.y);
        acc.z = fmaf(f23.x, wgt, acc.z);
        acc.w = fmaf(f23.y, wgt, acc.w);
        den += wgt;
    }
    // combine 8 edge slots (lane xor 4, 8, 16)
    #pragma unroll
    for (int bit = 4; bit <= 16; bit <<= 1) {
        acc.x += __shfl_xor_sync(FULLMASK, acc.x, bit);
        acc.y += __shfl_xor_sync(FULLMASK, acc.y, bit);
        acc.z += __shfl_xor_sync(FULLMASK, acc.z, bit);
        acc.w += __shfl_xor_sync(FULLMASK, acc.w, bit);
        den   += __shfl_xor_sync(FULLMASK, den,   bit);
    }

    float inv = 1.f / (den + 1e-16f);
    if (lane < 4) {
        int c = q4 * 4;
        float4 ev;
        ev.x = elu_fast(fmaf(acc.x, inv, sB2[c + 0]));
        ev.y = elu_fast(fmaf(acc.y, inv, sB2[c + 1]));
        ev.z = elu_fast(fmaf(acc.z, inv, sB2[c + 2]));
        ev.w = elu_fast(fmaf(acc.w, inv, sB2[c + 3]));
        *(float4*)&sEmb[w][c] = ev;
        if (out_size >= (long long)NNODES * OUT_DIM)
            *(float4*)&out[(long long)n * OUT_DIM + c] = ev;
    }
    __syncthreads();

    // classifier hidden layer: 128 threads, (node, k) pairs
    if (t < 128) {
        int nl = t >> 3, k = t & 7;
        float s = sBc1[k];
        #pragma unroll
        for (int o = 0; o < OUT_DIM; o++)
            s = fmaf(sEmb[nl][o], sWc1[o * 8 + k], s);
        sT[nl][k] = fmaxf(s, 0.f);
    }
    __syncthreads();

    // output layer + sigmoid: 16 threads
    if (t < 16) {
        float z = sBc2;
        #pragma unroll
        for (int k = 0; k < 8; k++) z = fmaf(sT[t][k], sWc2[k], z);
        float risk = 1.f / (1.f + __expf(-z));
        int gn = blockIdx.x * 16 + t;
        if (out_size >= (long long)NNODES * (OUT_DIM + 1))
            out[(long long)NNODES * OUT_DIM + gn] = risk;
        else if (out_size == (long long)NNODES)
            out[gn] = risk;
    }
}

// ---------------- launch ----------------
extern "C" void kernel_launch(void* const* d_in, const int* in_sizes, int n_in,
                              void* d_out, int out_size) {
    const float* x   = (const float*)d_in[0];
    const void*  ei  = d_in[1];
    const float* W1  = (const float*)d_in[2];
    const float* as1 = (const float*)d_in[3];
    const float* ad1 = (const float*)d_in[4];
    const float* b1  = (const float*)d_in[5];
    const float* W2  = (const float*)d_in[6];
    const float* as2 = (const float*)d_in[7];
    const float* ad2 = (const float*)d_in[8];
    const float* b2  = (const float*)d_in[9];
    const float* Wc1 = (const float*)d_in[10];
    const float* bc1 = (const float*)d_in[11];
    const float* Wc2 = (const float*)d_in[12];
    const float* bc2 = (const float*)d_in[13];

    // launch index:                                       0 (init + node1 fused)
    k_init<<<(NNODES + 255) / 256, 256>>>(ei, x, W1, as1, ad1);
    //                                                     1
    k_scatter<<<(NEDGES / 2 + 255) / 256, 256>>>(ei);
    //                                                     2
    k_agg1<<<NNODES / 8, 256>>>(x);
    //                                                     3  <- ncu window (dense)
    k_dense<<<(NNODES * 2 + 255) / 256, 256>>>(W1, b1, W2, as2, ad2);
    //                                                     4
    k_agg2<<<NNODES / 16, 512>>>(b2, Wc1, bc1, Wc2, bc2,
                                 (float*)d_out, (long long)out_size);
}

// round 14
// speedup vs baseline: 1.1246x; 1.1246x over previous
#include <cuda_runtime.h>
#include <cuda_fp16.h>

// ---------------- problem constants ----------------
#define NNODES 100000
#define NEDGES 1600000
#define IN_DIM 8
#define HID    32
#define HEADS  4
#define F1     (HEADS * HID)       // 128
#define OUT_DIM 16
#define STRIDE 128                 // fixed adjacency bucket per node
#define FULLMASK 0xffffffffu

// ---------------- scratch (device globals; no allocation allowed) ----------------
__device__ __align__(16) float g_as1[NNODES * HEADS];
__device__ __align__(16) float g_ad1[NNODES * HEADS];
__device__ __align__(16) float g_xagg[NNODES * 32];        // 12.8 MB x-space aggregates
__device__ __align__(16) __half g_h2h[NNODES * OUT_DIM];   // 3.2 MB fp16 layer-2 features
__device__ __align__(16) float g_as2[NNODES];
__device__ __align__(16) float g_ad2[NNODES];
__device__ __align__(16) int g_srcs[NNODES * STRIDE];      // stores src*4 (pre-scaled)
__device__ int g_cnt[NNODES];
__device__ int g_is64;

// ---------------- helpers ----------------
__device__ __forceinline__ float elu_fast(float v) {
    return v > 0.f ? v : (__expf(v) - 1.f);
}
__device__ __forceinline__ float lrelu_exp(float e) {
    e = fmaxf(e, 0.2f * e);
    return __expf(e);
}
__device__ __forceinline__ unsigned pack2(float a, float b) {
    __half2 h = __floats2half2_rn(a, b);
    return *(unsigned*)&h;
}

// ---------------- K init: bucket init + self loop + probe + layer-1 logits (fused node1) ----------------
__global__ void __launch_bounds__(256) k_init(
        const void* __restrict__ ei,
        const float* __restrict__ x, const float* __restrict__ W1,
        const float* __restrict__ as1v, const float* __restrict__ ad1v) {
    __shared__ float sVa[IN_DIM][HEADS], sVd[IN_DIM][HEADS];
    int t = threadIdx.x;
    if (t < IN_DIM * HEADS) {
        int d = t >> 2, h = t & 3;
        float sa = 0.f, sd = 0.f;
        #pragma unroll
        for (int k = 0; k < HID; k++) {
            float w = W1[d * F1 + h * HID + k];
            sa = fmaf(w, as1v[h * HID + k], sa);
            sd = fmaf(w, ad1v[h * HID + k], sd);
        }
        sVa[d][h] = sa;
        sVd[d][h] = sd;
    }
    if (blockIdx.x == 0 && t == 0) {
        const unsigned* wrd = (const unsigned*)ei;
        int is64 = 1;
        #pragma unroll
        for (int i = 0; i < 32; i++)
            if (wrd[2 * i + 1] != 0u) { is64 = 0; break; }
        g_is64 = is64;
    }
    __syncthreads();

    int n = blockIdx.x * blockDim.x + t;
    if (n >= NNODES) return;

    g_cnt[n] = 1;
    g_srcs[n * STRIDE] = n * 4;            // self loop in slot 0 (pre-scaled)

    float4 x0 = *(const float4*)(x + n * IN_DIM);
    float4 x1 = *(const float4*)(x + n * IN_DIM + 4);
    float xv[IN_DIM] = {x0.x, x0.y, x0.z, x0.w, x1.x, x1.y, x1.z, x1.w};
    float oa[HEADS] = {0.f, 0.f, 0.f, 0.f};
    float od[HEADS] = {0.f, 0.f, 0.f, 0.f};
    #pragma unroll
    for (int d = 0; d < IN_DIM; d++) {
        #pragma unroll
        for (int h = 0; h < HEADS; h++) {
            oa[h] = fmaf(xv[d], sVa[d][h], oa[h]);
            od[h] = fmaf(xv[d], sVd[d][h], od[h]);
        }
    }
    *(float4*)&g_as1[n * HEADS] = make_float4(oa[0], oa[1], oa[2], oa[3]);
    *(float4*)&g_ad1[n * HEADS] = make_float4(od[0], od[1], od[2], od[3]);
}

// ---------------- K scatter: real edges into fixed-stride buckets (2 per thread) ----------------
__global__ void k_scatter(const void* __restrict__ ei) {
    int base = (blockIdx.x * blockDim.x + threadIdx.x) * 2;
    if (base >= NEDGES) return;
    int s0, s1 = -1, d0, d1 = 0;
    if (g_is64) {
        const long long* ps = (const long long*)ei;
        const long long* pd = ps + NEDGES;
        longlong2 sv = *(const longlong2*)(ps + base);
        longlong2 dv = *(const longlong2*)(pd + base);
        s0 = (int)sv.x; d0 = (int)dv.x;
        if (base + 1 < NEDGES) { s1 = (int)sv.y; d1 = (int)dv.y; }
    } else {
        const int* ps = (const int*)ei;
        const int* pd = ps + NEDGES;
        int2 sv = *(const int2*)(ps + base);
        int2 dv = *(const int2*)(pd + base);
        s0 = sv.x; d0 = dv.x;
        if (base + 1 < NEDGES) { s1 = sv.y; d1 = dv.y; }
    }
    int k0 = atomicAdd(&g_cnt[d0], 1);
    if (k0 < STRIDE) g_srcs[d0 * STRIDE + k0] = s0 * 4;
    if (s1 >= 0) {
        int k1 = atomicAdd(&g_cnt[d1], 1);
        if (k1 < STRIDE) g_srcs[d1 * STRIDE + k1] = s1 * 4;
    }
}

// ---------------- K agg1: edge loop ONLY -> normalized x-space aggregates ----------------
// warp per node; slot g = lane>>3 (4 edges/iter), hd = lane&7: head = hd&3, dq = hd>>2
__global__ void __launch_bounds__(256) k_agg1(const float* __restrict__ x) {
    int w = threadIdx.x >> 5, lane = threadIdx.x & 31;
    int n = blockIdx.x * 8 + w;              // 12500*8 == 100000
    int g = lane >> 3;
    int hd = lane & 7;
    int head = hd & 3;
    int dqc = (hd >> 2) * 4;                 // 0 or 4

    float ad_h = g_ad1[n * HEADS + head];
    int cnt = min(g_cnt[n], STRIDE);
    const int* my_srcs = &g_srcs[n * STRIDE];

    float4 acc = make_float4(0.f, 0.f, 0.f, 0.f);
    float den = 0.f;

    #pragma unroll 2
    for (int base = 0; base < cnt; base += 4) {
        int i = base + g;
        bool valid = i < cnt;
        int s4 = my_srcs[valid ? i : 0];     // slot 0 (self loop) always valid
        float e = g_as1[s4 + head];
        float4 xv = *(const float4*)(x + (s4 << 1) + dqc);
        float wgt = valid ? lrelu_exp(e + ad_h) : 0.f;
        acc.x = fmaf(xv.x, wgt, acc.x);
        acc.y = fmaf(xv.y, wgt, acc.y);
        acc.z = fmaf(xv.z, wgt, acc.z);
        acc.w = fmaf(xv.w, wgt, acc.w);
        den += wgt;
    }

    // combine the 4 edge slots (lane xor 8, 16)
    #pragma unroll
    for (int bit = 8; bit <= 16; bit <<= 1) {
        acc.x += __shfl_xor_sync(FULLMASK, acc.x, bit);
        acc.y += __shfl_xor_sync(FULLMASK, acc.y, bit);
        acc.z += __shfl_xor_sync(FULLMASK, acc.z, bit);
        acc.w += __shfl_xor_sync(FULLMASK, acc.w, bit);
        den   += __shfl_xor_sync(FULLMASK, den,   bit);
    }

    if (g == 0) {
        float inv = 1.f / (den + 1e-16f);
        float4 o = make_float4(acc.x * inv, acc.y * inv, acc.z * inv, acc.w * inv);
        *(float4*)&g_xagg[n * 32 + hd * 4] = o;   // 8 lanes x 16B = 128B coalesced
    }
}

// ---------------- K dense (R11 form): thread-per-node; warp-uniform smem reads ----------------
// hc = elu(xagg@W1+b1); h2 = hc@W2; layer-2 logits. All smem loads broadcast.
__global__ void __launch_bounds__(256) k_dense(
        const float* __restrict__ W1, const float* __restrict__ b1,
        const float* __restrict__ W2,
        const float* __restrict__ as2v, const float* __restrict__ ad2v) {
    __shared__ __align__(16) float sW1[IN_DIM][F1];      // [d][c]
    __shared__ __align__(16) float sW2[F1][OUT_DIM];     // [c][o]
    __shared__ __align__(16) float sB1[F1];
    __shared__ float sAs[OUT_DIM], sAd[OUT_DIM];
    int t = threadIdx.x;
    for (int i = t; i < IN_DIM * F1; i += 256) ((float*)sW1)[i] = W1[i];
    for (int i = t; i < F1 * OUT_DIM; i += 256) ((float*)sW2)[i] = W2[i];
    if (t < F1) sB1[t] = b1[t];
    if (t < OUT_DIM) { sAs[t] = as2v[t]; sAd[t] = ad2v[t]; }
    __syncthreads();

    int n = blockIdx.x * 256 + t;
    if (n >= NNODES) return;

    float xa[32];
    #pragma unroll
    for (int i = 0; i < 8; i++)
        *(float4*)&xa[i * 4] = ((const float4*)g_xagg)[n * 8 + i];

    float p[OUT_DIM];
    #pragma unroll
    for (int o = 0; o < OUT_DIM; o++) p[o] = 0.f;

    #pragma unroll
    for (int h = 0; h < HEADS; h++) {
        // head-h slice of xagg (static indexing)
        float x8[8];
        #pragma unroll
        for (int d = 0; d < 4; d++) {
            x8[d]     = xa[h * 4 + d];        // dq=0 block
            x8[d + 4] = xa[h * 4 + 16 + d];   // dq=1 block
        }
        #pragma unroll 1
        for (int cq = 0; cq < 8; cq++) {
            int c = h * 32 + cq * 4;
            float4 hc = *(const float4*)&sB1[c];
            #pragma unroll
            for (int d = 0; d < IN_DIM; d++) {
                float4 wv = *(const float4*)&sW1[d][c];
                hc.x = fmaf(x8[d], wv.x, hc.x);
                hc.y = fmaf(x8[d], wv.y, hc.y);
                hc.z = fmaf(x8[d], wv.z, hc.z);
                hc.w = fmaf(x8[d], wv.w, hc.w);
            }
            hc.x = elu_fast(hc.x);
            hc.y = elu_fast(hc.y);
            hc.z = elu_fast(hc.z);
            hc.w = elu_fast(hc.w);
            float hcv[4] = {hc.x, hc.y, hc.z, hc.w};
            #pragma unroll
            for (int k = 0; k < 4; k++) {
                #pragma unroll
                for (int o4 = 0; o4 < 4; o4++) {
                    float4 wv = *(const float4*)&sW2[c + k][o4 * 4];
                    p[o4 * 4 + 0] = fmaf(hcv[k], wv.x, p[o4 * 4 + 0]);
                    p[o4 * 4 + 1] = fmaf(hcv[k], wv.y, p[o4 * 4 + 1]);
                    p[o4 * 4 + 2] = fmaf(hcv[k], wv.z, p[o4 * 4 + 2]);
                    p[o4 * 4 + 3] = fmaf(hcv[k], wv.w, p[o4 * 4 + 3]);
                }
            }
        }
    }

    // h2 in fp16 (32B per node, contiguous)
    uint4 u0, u1;
    u0.x = pack2(p[0],  p[1]);  u0.y = pack2(p[2],  p[3]);
    u0.z = pack2(p[4],  p[5]);  u0.w = pack2(p[6],  p[7]);
    u1.x = pack2(p[8],  p[9]);  u1.y = pack2(p[10], p[11]);
    u1.z = pack2(p[12], p[13]); u1.w = pack2(p[14], p[15]);
    ((uint4*)g_h2h)[n * 2 + 0] = u0;
    ((uint4*)g_h2h)[n * 2 + 1] = u1;

    float ts = 0.f, td = 0.f;
    #pragma unroll
    for (int o = 0; o < OUT_DIM; o++) {
        ts = fmaf(p[o], sAs[o], ts);
        td = fmaf(p[o], sAd[o], td);
    }
    g_as2[n] = ts;
    g_ad2[n] = td;
}

// ---------------- K agg2: layer-2 aggregate (8 edges/warp/iter, fp16 gather) + classifier ----------------
__global__ void __launch_bounds__(512) k_agg2(
        const float* __restrict__ b2, const float* __restrict__ Wc1,
        const float* __restrict__ bc1, const float* __restrict__ Wc2,
        const float* __restrict__ bc2, float* __restrict__ out,
        long long out_size) {
    __shared__ __align__(16) float sEmb[16][OUT_DIM + 4];  // 80B rows (16B multiple)
    __shared__ float sT[16][9];
    __shared__ float sWc1[OUT_DIM * 8];
    __shared__ float sWc2[8], sB2[OUT_DIM];
    __shared__ float sBc1[8], sBc2;
    int t = threadIdx.x;
    if (t < OUT_DIM * 8) sWc1[t] = Wc1[t];
    if (t >= 128 && t < 136) sWc2[t - 128] = Wc2[t - 128];
    if (t >= 136 && t < 144) sBc1[t - 136] = bc1[t - 136];
    if (t >= 144 && t < 160) sB2[t - 144] = b2[t - 144];
    if (t == 160) sBc2 = bc2[0];
    __syncthreads();

    int w = t >> 5, lane = t & 31;
    int n = blockIdx.x * 16 + w;
    int g2 = lane >> 2;        // edge slot 0..7
    int q4 = lane & 3;         // channel quad 4q4..4q4+3

    float ad_n = g_ad2[n];
    int cnt = min(g_cnt[n], STRIDE);
    const int* my_srcs = &g_srcs[n * STRIDE];

    float4 acc = make_float4(0.f, 0.f, 0.f, 0.f);
    float den = 0.f;

    for (int base = 0; base < cnt; base += 8) {
        int i = base + g2;
        bool valid = i < cnt;
        int s4 = my_srcs[valid ? i : 0];
        float e = g_as2[s4 >> 2];
        uint2 hv = ((const uint2*)g_h2h)[s4 + q4];        // 8B = 4 fp16 channels
        float wgt = valid ? lrelu_exp(e + ad_n) : 0.f;
        float2 f01 = __half22float2(*(const __half2*)&hv.x);
        float2 f23 = __half22float2(*(const __half2*)&hv.y);
        acc.x = fmaf(f01.x, wgt, acc.x);
        acc.y = fmaf(f01.y, wgt, acc.y);
        acc.z = fmaf(f23.x, wgt, acc.z);
        acc.w = fmaf(f23.y, wgt, acc.w);
        den += wgt;
    }
    // combine 8 edge slots (lane xor 4, 8, 16)
    #pragma unroll
    for (int bit = 4; bit <= 16; bit <<= 1) {
        acc.x += __shfl_xor_sync(FULLMASK, acc.x, bit);
        acc.y += __shfl_xor_sync(FULLMASK, acc.y, bit);
        acc.z += __shfl_xor_sync(FULLMASK, acc.z, bit);
        acc.w += __shfl_xor_sync(FULLMASK, acc.w, bit);
        den   += __shfl_xor_sync(FULLMASK, den,   bit);
    }

    float inv = 1.f / (den + 1e-16f);
    if (lane < 4) {
        int c = q4 * 4;
        float4 ev;
        ev.x = elu_fast(fmaf(acc.x, inv, sB2[c + 0]));
        ev.y = elu_fast(fmaf(acc.y, inv, sB2[c + 1]));
        ev.z = elu_fast(fmaf(acc.z, inv, sB2[c + 2]));
        ev.w = elu_fast(fmaf(acc.w, inv, sB2[c + 3]));
        *(float4*)&sEmb[w][c] = ev;
        if (out_size >= (long long)NNODES * OUT_DIM)
            *(float4*)&out[(long long)n * OUT_DIM + c] = ev;
    }
    __syncthreads();

    // classifier hidden layer: 128 threads, (node, k) pairs
    if (t < 128) {
        int nl = t >> 3, k = t & 7;
        float s = sBc1[k];
        #pragma unroll
        for (int o = 0; o < OUT_DIM; o++)
            s = fmaf(sEmb[nl][o], sWc1[o * 8 + k], s);
        sT[nl][k] = fmaxf(s, 0.f);
    }
    __syncthreads();

    // output layer + sigmoid: 16 threads
    if (t < 16) {
        float z = sBc2;
        #pragma unroll
        for (int k = 0; k < 8; k++) z = fmaf(sT[t][k], sWc2[k], z);
        float risk = 1.f / (1.f + __expf(-z));
        int gn = blockIdx.x * 16 + t;
        if (out_size >= (long long)NNODES * (OUT_DIM + 1))
            out[(long long)NNODES * OUT_DIM + gn] = risk;
        else if (out_size == (long long)NNODES)
            out[gn] = risk;
    }
}

// ---------------- launch ----------------
extern "C" void kernel_launch(void* const* d_in, const int* in_sizes, int n_in,
                              void* d_out, int out_size) {
    const float* x   = (const float*)d_in[0];
    const void*  ei  = d_in[1];
    const float* W1  = (const float*)d_in[2];
    const float* as1 = (const float*)d_in[3];
    const float* ad1 = (const float*)d_in[4];
    const float* b1  = (const float*)d_in[5];
    const float* W2  = (const float*)d_in[6];
    const float* as2 = (const float*)d_in[7];
    const float* ad2 = (const float*)d_in[8];
    const float* b2  = (const float*)d_in[9];
    const float* Wc1 = (const float*)d_in[10];
    const float* bc1 = (const float*)d_in[11];
    const float* Wc2 = (const float*)d_in[12];
    const float* bc2 = (const float*)d_in[13];

    // launch index:                                       0 (init + node1 fused)
    k_init<<<(NNODES + 255) / 256, 256>>>(ei, x, W1, as1, ad1);
    //                                                     1
    k_scatter<<<(NEDGES / 2 + 255) / 256, 256>>>(ei);
    //                                                     2
    k_agg1<<<NNODES / 8, 256>>>(x);
    //                                                     3  <- ncu window (dense)
    k_dense<<<(NNODES + 255) / 256, 256>>>(W1, b1, W2, as2, ad2);
    //                                                     4
    k_agg2<<<NNODES / 16, 512>>>(b2, Wc1, bc1, Wc2, bc2,
                                 (float*)d_out, (long long)out_size);
}